// round 12
// baseline (speedup 1.0000x reference)
#include <cuda_runtime.h>

// ---------------------------------------------------------------------------
// PhotonicLayer via TF32 tensor cores (mma.sync.m16n8k8), fragment-packed.
// Real GEMM: X=[xr|xi] (Bx128), W=[[Ur,-Ui],[Ui,Ur]] (128x128), out'=X@W^T.
// K1: build U with each column fully register-resident (2016-step scan fully
//     unrolled, static register indices, no barriers), emit W in B-fragment
//     uint4 order (2 k-steps per LDG.128).
// K2: tensor-core GEMM, A fragment-packed in smem (LDS.128), register
//     epilogue (re/im pairing in-warp), direct float2 stores.
// ---------------------------------------------------------------------------

#define SIZE 64
#define NPH 2016
#define LOSS_AMP 0.9942600740f      // 10^(-0.05/20)
#define KERR 2.6e-17f               // NONLINEAR_COEFF * 1000

// W fragment-packed, uint4 per (n8t, ks2, lane):
//   word idx = ((n8t*8 + ks2)*32 + lane)*4 + ksLo*2 + q
__device__ uint4 g_Wfrag4[16 * 8 * 32];   // 64 KB

// ---------------------------- build kernel --------------------------------
__device__ __forceinline__ void w_store(unsigned* Wf, int np, int kp, float v) {
    unsigned tv;
    asm("cvt.rna.tf32.f32 %0, %1;" : "=r"(tv) : "f"(v));
    const int n8t = np >> 3, g = np & 7;
    const int ks = kp >> 3, ks2 = ks >> 1, ksLo = ks & 1;
    const int t4 = kp & 3, q = (kp >> 2) & 1;
    const int lane = g * 4 + t4;
    Wf[(((n8t * 8 + ks2) * 32 + lane) << 2) + ksLo * 2 + q] = tv;
}

__global__ __launch_bounds__(64)
void build_u_kernel(const float* __restrict__ phases, int nph) {
    __shared__ float2 ang[NPH];      // (L*cos, L*sin) per rotation, 16 KB

    const int t = threadIdx.x;       // column 0..63
    const int pmax = (nph > 0) ? (nph - 1) : 0;

    for (int k = t; k < NPH; k += 64) {
        const int kk = (k < pmax) ? k : pmax;
        float sv, cv;
        sincosf(phases[kk], &sv, &cv);
        ang[k] = make_float2(LOSS_AMP * cv, LOSS_AMP * sv);
    }
    __syncthreads();

    // column t of U lives entirely in registers (static indices after unroll)
    float ur[SIZE], ui[SIZE];
    #pragma unroll
    for (int r = 0; r < SIZE; ++r) {
        ur[r] = (r == t) ? 1.0f : 0.0f;
        ui[r] = 0.0f;
    }

    #pragma unroll
    for (int i = 1; i < SIZE; ++i) {
        #pragma unroll
        for (int j = 0; j < i; ++j) {
            const int k = ((i * (i - 1)) >> 1) + j;
            const float2 a2 = ang[k];          // warp-uniform broadcast LDS
            const float cc = a2.x, ss = a2.y;
            const float ar = ur[j],     ai = ui[j];
            const float br = ur[j + 1], bi = ui[j + 1];
            ur[j]     = fmaf(cc, ar, -(ss * bi));
            ui[j]     = fmaf(cc, ai,   ss * br);
            ur[j + 1] = fmaf(cc, br, -(ss * ai));
            ui[j + 1] = fmaf(cc, bi,   ss * ar);
        }
    }

    // Thread t supplies W columns k' = t and t+64 for all 128 n':
    //   n'<64:  [ Ur | -Ui ] ; n'>=64: [ Ui | Ur ]
    unsigned* Wf = (unsigned*)g_Wfrag4;
    #pragma unroll
    for (int n = 0; n < SIZE; ++n) {
        w_store(Wf, n,      t,       ur[n]);
        w_store(Wf, n,      t + 64, -ui[n]);
        w_store(Wf, n + 64, t,       ui[n]);
        w_store(Wf, n + 64, t + 64,  ur[n]);
    }
}

// ----------------------------- GEMM kernel --------------------------------
// 256 threads (8 warps: warpM 0..1 x warpN 0..3). Tile: 128 b x 128 n', K=128.
// warpN owns n8-tiles {2w, 2w+1, 2w+8, 2w+9} -> re/im pair in-warp.
__global__ __launch_bounds__(256, 2)
void photonic_mma_kernel(const float* __restrict__ xr_g,
                         const float* __restrict__ xi_g,
                         float* __restrict__ out,
                         long long xsz, long long out_elems, int B) {
    extern __shared__ char smem[];
    unsigned* sxA = (unsigned*)smem;          // packed A: 64 KB

    const int tid  = threadIdx.x;
    const int lane = tid & 31;
    const int warp = tid >> 5;
    const int g = lane >> 2;
    const int t = lane & 3;
    const int warpM = warp >> 2;              // 0..1
    const int warpN = warp & 3;               // 0..3

    const long long b0 = (long long)blockIdx.x * 128;
    if (b0 >= B) return;
    const long long base = b0 * SIZE;
    const long long xmax = xsz - 1;

    // ---- stage X = [xr | xi], tf32-rounded, in A-fragment order ----
    for (int p = tid; p < 128 * 64; p += 256) {
        const int bb = p >> 6, k = p & 63;
        long long gi = base + p;
        if (gi > xmax) gi = xmax;
        const float vr = xr_g[gi];
        const float vi = xi_g[gi];
        unsigned r_, i_;
        asm("cvt.rna.tf32.f32 %0, %1;" : "=r"(r_) : "f"(vr));
        asm("cvt.rna.tf32.f32 %0, %1;" : "=r"(i_) : "f"(vi));
        const int m16t = bb >> 4, gg = bb & 7, half = (bb >> 3) & 1;
        const int tt = k & 3, q = (k >> 2) & 1;
        const int bse = (m16t * 16) * 128 + (gg * 4 + tt) * 4 + half + 2 * q;
        sxA[bse + ((k >> 3)) * 128]     = r_;   // re: ks = k>>3
        sxA[bse + ((k >> 3) + 8) * 128] = i_;   // im: ks = k>>3 + 8
    }
    __syncthreads();

    // ---- accumulators: c[mt][cidx][4]; cidx 0,1 = re tiles, 2,3 = im ----
    float c[4][4][4];
    #pragma unroll
    for (int mt = 0; mt < 4; ++mt)
        #pragma unroll
        for (int nt = 0; nt < 4; ++nt)
            #pragma unroll
            for (int q2 = 0; q2 < 4; ++q2) c[mt][nt][q2] = 0.0f;

    // n8-tile ids for this warp: {2w, 2w+1, 2w+8, 2w+9}
    int n8tab[4];
    n8tab[0] = warpN * 2;     n8tab[1] = warpN * 2 + 1;
    n8tab[2] = warpN * 2 + 8; n8tab[3] = warpN * 2 + 9;

    #pragma unroll 2
    for (int ks2 = 0; ks2 < 8; ++ks2) {
        uint4 bf4[4];
        #pragma unroll
        for (int nt = 0; nt < 4; ++nt)
            bf4[nt] = __ldg(&g_Wfrag4[(n8tab[nt] * 8 + ks2) * 32 + lane]);
        #pragma unroll
        for (int kl = 0; kl < 2; ++kl) {
            const int ks = ks2 * 2 + kl;
            uint4 a[4];
            #pragma unroll
            for (int mt = 0; mt < 4; ++mt)
                a[mt] = *(const uint4*)&sxA[(((warpM * 4 + mt) * 16 + ks) * 32
                                             + lane) * 4];
            #pragma unroll
            for (int mt = 0; mt < 4; ++mt)
                #pragma unroll
                for (int nt = 0; nt < 4; ++nt) {
                    const unsigned bx = kl ? bf4[nt].z : bf4[nt].x;
                    const unsigned by = kl ? bf4[nt].w : bf4[nt].y;
                    asm volatile(
                        "mma.sync.aligned.m16n8k8.row.col.f32.tf32.tf32.f32 "
                        "{%0,%1,%2,%3}, {%4,%5,%6,%7}, {%8,%9}, {%0,%1,%2,%3};"
                        : "+f"(c[mt][nt][0]), "+f"(c[mt][nt][1]),
                          "+f"(c[mt][nt][2]), "+f"(c[mt][nt][3])
                        : "r"(a[mt].x), "r"(a[mt].y), "r"(a[mt].z), "r"(a[mt].w),
                          "r"(bx), "r"(by));
                }
        }
    }

    // ---- register epilogue: pair re (cidx) with im (cidx+2), Kerr, store ----
    #pragma unroll
    for (int mt = 0; mt < 4; ++mt) {
        const int row0 = warpM * 64 + mt * 16 + g;
        #pragma unroll
        for (int ci = 0; ci < 2; ++ci) {
            const int n = (warpN * 2 + ci) * 8 + 2 * t;
            #pragma unroll
            for (int h = 0; h < 2; ++h) {
                const int row = row0 + 8 * h;
                const float re0 = c[mt][ci][2 * h];
                const float re1 = c[mt][ci][2 * h + 1];
                const float im0 = c[mt][ci + 2][2 * h];
                const float im1 = c[mt][ci + 2][2 * h + 1];
                const float ph0 = KERR * fmaf(re0, re0, im0 * im0);
                const float ph1 = KERR * fmaf(re1, re1, im1 * im1);
                const long long o = base + (long long)row * 64 + n;
                if (o + 2 <= out_elems)
                    *(float2*)&out[o] = make_float2(fmaf(-im0, ph0, re0),
                                                    fmaf(-im1, ph1, re1));
            }
        }
    }
}

// ------------------------------- launch ------------------------------------
extern "C" void kernel_launch(void* const* d_in, const int* in_sizes, int n_in,
                              void* d_out, int out_size) {
    if (n_in < 3) return;

    // phases = the input with the smallest element count (2016 vs B*64)
    int ph_idx = 0;
    for (int i = 1; i < 3; ++i)
        if (in_sizes[i] < in_sizes[ph_idx]) ph_idx = i;

    const float* xr = nullptr;
    const float* xi = nullptr;
    long long xsz = 0;
    for (int i = 0; i < 3; ++i) {
        if (i == ph_idx) continue;
        if (!xr) { xr = (const float*)d_in[i]; xsz = in_sizes[i]; }
        else     { xi = (const float*)d_in[i]; }
    }
    const float* phases = (const float*)d_in[ph_idx];
    const int nph = in_sizes[ph_idx];

    const int B = (int)(xsz / SIZE);
    const int nblocks = (B + 127) / 128;

    cudaFuncSetAttribute(photonic_mma_kernel,
                         cudaFuncAttributeMaxDynamicSharedMemorySize,
                         65536);

    build_u_kernel<<<1, 64>>>(phases, nph);
    photonic_mma_kernel<<<nblocks, 256, 65536>>>(
        xr, xi, (float*)d_out, xsz, (long long)out_size, B);
}

// round 13
// speedup vs baseline: 1.1771x; 1.1771x over previous
#include <cuda_runtime.h>

// ---------------------------------------------------------------------------
// PhotonicLayer via TF32 tensor cores (mma.sync.m16n8k8), fragment-packed.
// Real GEMM: X=[xr|xi] (Bx128), W=[[Ur,-Ui],[Ui,Ur]] (128x128), out'=X@W^T.
// A (X) staged in smem in fragment order with a bank-perfect lane mapping
// (32 distinct banks per STS warp-inst). B prepacked in fragment order.
// Register epilogue: re/im pairing in-warp, Kerr, direct float2 stores.
// ---------------------------------------------------------------------------

#define SIZE 64
#define NPH 2016
#define LOSS_AMP 0.9942600740f      // 10^(-0.05/20)
#define KERR 2.6e-17f               // NONLINEAR_COEFF * 1000
#define BT 672                      // build threads = 21 warps (widest wave)

// W in fragment order: flat idx = (((n8t*16 + ks)*32 + lane)*2 + q)
__device__ unsigned g_Wfrag[16 * 16 * 32 * 2];   // 64 KB

// ---------------------------- build kernel --------------------------------
// Wavefront schedule: rotation (i,j) at T = 2i+j; same-T rotations touch
// disjoint row pairs -> in-place, one barrier per wavefront (187 waves,
// which equals the dependency critical path).
__global__ __launch_bounds__(BT)
void build_u_kernel(const float* __restrict__ phases, int nph) {
    __shared__ float2 S[SIZE][SIZE];    // [row][col] = U
    __shared__ float cs[NPH];
    __shared__ float sn[NPH];

    const int tid  = threadIdx.x;
    const int lane = tid & 31;
    const int warp = tid >> 5;
    const int pmax = (nph > 0) ? (nph - 1) : 0;

    for (int k = tid; k < NPH; k += BT) {
        const int kk = (k < pmax) ? k : pmax;
        float sv, cv;
        sincosf(phases[kk], &sv, &cv);
        cs[k] = LOSS_AMP * cv;
        sn[k] = LOSS_AMP * sv;
    }
    for (int p = tid; p < SIZE * SIZE; p += BT) {
        const int r = p >> 6, c = p & 63;
        S[r][c] = make_float2(r == c ? 1.0f : 0.0f, 0.0f);
    }
    __syncthreads();

    for (int w = 2; w <= 188; ++w) {
        int i_min = (w + 3) / 3;
        if (i_min < 1) i_min = 1;
        int i_max = w >> 1;
        if (i_max > 63) i_max = 63;
        const int cnt = i_max - i_min + 1;   // <= 21

        if (warp < cnt) {
            const int i = i_min + warp;
            const int j = w - 2 * i;
            const int k = ((i * (i - 1)) >> 1) + j;
            const float cc = cs[k], ss = sn[k];
            #pragma unroll
            for (int h = 0; h < 2; ++h) {
                const int c = lane + 32 * h;
                const float2 a = S[j][c];
                const float2 b = S[j + 1][c];
                const float nar = fmaf(cc, a.x, -(ss * b.y));
                const float nai = fmaf(cc, a.y,   ss * b.x);
                const float nbr = fmaf(cc, b.x, -(ss * a.y));
                const float nbi = fmaf(cc, b.y,   ss * a.x);
                S[j][c]     = make_float2(nar, nai);
                S[j + 1][c] = make_float2(nbr, nbi);
            }
        }
        __syncthreads();
    }

    // emit W[n'][k'] tf32-rounded in mma B-fragment order:
    //   n'<64: [ Ur | -Ui ] ; n'>=64: [ Ui | Ur ]
    for (int p = tid; p < 128 * 128; p += BT) {
        const int n = p >> 7, k = p & 127;
        const float2 u = S[n & 63][k & 63];
        float v;
        if (n < 64) v = (k < 64) ? u.x : -u.y;
        else        v = (k < 64) ? u.y :  u.x;
        unsigned tv;
        asm("cvt.rna.tf32.f32 %0, %1;" : "=r"(tv) : "f"(v));
        const int n8t = n >> 3, g = n & 7;
        const int ks = k >> 3, t = k & 3, q = (k >> 2) & 1;
        g_Wfrag[(((n8t * 16 + ks) * 32 + g * 4 + t) << 1) + q] = tv;
    }
}

// ----------------------------- GEMM kernel --------------------------------
// 256 threads (8 warps: warpM 0..1 x warpN 0..3). Tile: 128 b x 128 n', K=128.
// warpN owns n8-tiles {2w, 2w+1, 2w+8, 2w+9} -> re/im pairing in registers.
__global__ __launch_bounds__(256, 2)
void photonic_mma_kernel(const float* __restrict__ xr_g,
                         const float* __restrict__ xi_g,
                         float* __restrict__ out,
                         long long xsz, long long out_elems, int B) {
    extern __shared__ char smem[];
    unsigned* sxA = (unsigned*)smem;          // packed A: 64 KB

    const int tid  = threadIdx.x;
    const int lane = tid & 31;
    const int warp = tid >> 5;
    const int g = lane >> 2;                  // groupID 0..7
    const int t = lane & 3;                   // thread-in-group 0..3
    const int warpM = warp >> 2;              // 0..1
    const int warpN = warp & 3;               // 0..3

    const long long b0 = (long long)blockIdx.x * 128;
    if (b0 >= B) return;
    const long long base = b0 * SIZE;
    const long long xmax = xsz - 1;

    // ---- stage X = [xr | xi], tf32-rounded, A-fragment order ----
    // Lane mapping chosen so STS banks are all-distinct within a warp:
    //   bank = 16*(bb&1) + 4*(k&3) + ((bb>>3)&1) + 2*((k>>2)&1)
    //   idx bits: 0->bb0, 1->bb3, 2..3->k0..1, 4->k2 (5 lane bits),
    //             5..7->k3..5, 8..9->bb1..2, 10..12->bb4..6
    #pragma unroll 4
    for (int it = 0; it < 32; ++it) {
        const int idx = it * 256 + tid;
        const int bb = (idx & 1) | (((idx >> 8) & 3) << 1)
                     | (((idx >> 1) & 1) << 3) | (((idx >> 10) & 7) << 4);
        const int k  = ((idx >> 2) & 3) | (((idx >> 4) & 1) << 2)
                     | (((idx >> 5) & 7) << 3);
        long long gi = base + (long long)bb * 64 + k;
        if (gi > xmax) gi = xmax;
        const float vr = xr_g[gi];
        const float vi = xi_g[gi];
        unsigned r_, i_;
        asm("cvt.rna.tf32.f32 %0, %1;" : "=r"(r_) : "f"(vr));
        asm("cvt.rna.tf32.f32 %0, %1;" : "=r"(i_) : "f"(vi));
        const int m16t = bb >> 4, gg = bb & 7, half = (bb >> 3) & 1;
        const int tt = k & 3, q = (k >> 2) & 1;
        const int bse = (m16t * 16) * 128 + (gg * 4 + tt) * 4 + half + 2 * q;
        sxA[bse + ((k >> 3)) * 128]     = r_;   // re: ks = k>>3
        sxA[bse + ((k >> 3) + 8) * 128] = i_;   // im: ks = k>>3 + 8
    }
    __syncthreads();

    // ---- accumulators: c[mt][cidx][4]; cidx 0,1 = re tiles, 2,3 = im ----
    float c[4][4][4];
    #pragma unroll
    for (int mt = 0; mt < 4; ++mt)
        #pragma unroll
        for (int nt = 0; nt < 4; ++nt)
            #pragma unroll
            for (int q2 = 0; q2 < 4; ++q2) c[mt][nt][q2] = 0.0f;

    // n8-tile ids for this warp: {2w, 2w+1, 2w+8, 2w+9}
    int n8tab[4];
    n8tab[0] = warpN * 2;     n8tab[1] = warpN * 2 + 1;
    n8tab[2] = warpN * 2 + 8; n8tab[3] = warpN * 2 + 9;

    #pragma unroll 4
    for (int ks = 0; ks < 16; ++ks) {
        uint4 a[4];
        #pragma unroll
        for (int mt = 0; mt < 4; ++mt)
            a[mt] = *(const uint4*)&sxA[(((warpM * 4 + mt) * 16 + ks) * 32
                                         + lane) * 4];
        uint2 bf[4];
        #pragma unroll
        for (int nt = 0; nt < 4; ++nt)
            bf[nt] = __ldg((const uint2*)&g_Wfrag[
                (((n8tab[nt] * 16 + ks) * 32 + lane) << 1)]);
        #pragma unroll
        for (int mt = 0; mt < 4; ++mt)
            #pragma unroll
            for (int nt = 0; nt < 4; ++nt)
                asm volatile(
                    "mma.sync.aligned.m16n8k8.row.col.f32.tf32.tf32.f32 "
                    "{%0,%1,%2,%3}, {%4,%5,%6,%7}, {%8,%9}, {%0,%1,%2,%3};"
                    : "+f"(c[mt][nt][0]), "+f"(c[mt][nt][1]),
                      "+f"(c[mt][nt][2]), "+f"(c[mt][nt][3])
                    : "r"(a[mt].x), "r"(a[mt].y), "r"(a[mt].z), "r"(a[mt].w),
                      "r"(bf[nt].x), "r"(bf[nt].y));
    }

    // ---- register epilogue: pair re (cidx) with im (cidx+2), Kerr, store ----
    #pragma unroll
    for (int mt = 0; mt < 4; ++mt) {
        const int row0 = warpM * 64 + mt * 16 + g;
        #pragma unroll
        for (int ci = 0; ci < 2; ++ci) {
            const int n = (warpN * 2 + ci) * 8 + 2 * t;
            #pragma unroll
            for (int h = 0; h < 2; ++h) {
                const int row = row0 + 8 * h;
                const float re0 = c[mt][ci][2 * h];
                const float re1 = c[mt][ci][2 * h + 1];
                const float im0 = c[mt][ci + 2][2 * h];
                const float im1 = c[mt][ci + 2][2 * h + 1];
                const float ph0 = KERR * fmaf(re0, re0, im0 * im0);
                const float ph1 = KERR * fmaf(re1, re1, im1 * im1);
                const long long o = base + (long long)row * 64 + n;
                if (o + 2 <= out_elems)
                    *(float2*)&out[o] = make_float2(fmaf(-im0, ph0, re0),
                                                    fmaf(-im1, ph1, re1));
            }
        }
    }
}

// ------------------------------- launch ------------------------------------
extern "C" void kernel_launch(void* const* d_in, const int* in_sizes, int n_in,
                              void* d_out, int out_size) {
    if (n_in < 3) return;

    // phases = the input with the smallest element count (2016 vs B*64)
    int ph_idx = 0;
    for (int i = 1; i < 3; ++i)
        if (in_sizes[i] < in_sizes[ph_idx]) ph_idx = i;

    const float* xr = nullptr;
    const float* xi = nullptr;
    long long xsz = 0;
    for (int i = 0; i < 3; ++i) {
        if (i == ph_idx) continue;
        if (!xr) { xr = (const float*)d_in[i]; xsz = in_sizes[i]; }
        else     { xi = (const float*)d_in[i]; }
    }
    const float* phases = (const float*)d_in[ph_idx];
    const int nph = in_sizes[ph_idx];

    const int B = (int)(xsz / SIZE);
    const int nblocks = (B + 127) / 128;

    cudaFuncSetAttribute(photonic_mma_kernel,
                         cudaFuncAttributeMaxDynamicSharedMemorySize,
                         65536);

    build_u_kernel<<<1, BT>>>(phases, nph);
    photonic_mma_kernel<<<nblocks, 256, 65536>>>(
        xr, xi, (float*)d_out, xsz, (long long)out_size, B);
}